// round 4
// baseline (speedup 1.0000x reference)
#include <cuda_runtime.h>
#include <math.h>

// Fixed problem shapes: N=8192 atoms, E=32768 edges (guarded loads for safety).
#define N_MAX 8192
#define E_MAX 32768
#define NCH   8          // j-dimension chunks in steric kernel (grid.y): 32*8=256 blocks, all co-resident
#define TILE  512        // smem tile of float4 per inner sweep

// ---------------- device scratch (no allocations allowed) ----------------
__device__ int    g_counts[N_MAX];
__device__ int    g_cursor[N_MAX];
__device__ int    g_off[N_MAX + 1];
__device__ int    g_csr[E_MAX];
__device__ float  g_viol[N_MAX];
__device__ float  g_rad8[N_MAX];     // 0.8 * vdw radius per atom
__device__ float  g_pA[N_MAX * 3];   // sweep ping
__device__ float  g_pB[N_MAX * 3];   // sweep pong
__device__ float  g_pos2[N_MAX * 3]; // after bond-length correction (atomics)
__device__ float4 g_pack[N_MAX];     // (x,y,z,rad8) packed for steric tiles
__device__ float4 g_part[NCH * N_MAX]; // per-chunk partial (csum, cvec)
__device__ float  g_loss1;
__device__ float  g_l2part[256];
__device__ float  g_l3part[256];
// chemistry tables
__device__ float  t_maxv[54];
__device__ float  t_vdw[54];
__device__ float  t_bond[54 * 54];

// ---------------- K0: tables + zero counters ----------------
__global__ void k_init(int N) {
    int tid = threadIdx.x;
    for (int i = tid; i < 54; i += blockDim.x) { t_maxv[i] = 4.0f; t_vdw[i] = 1.6f; }
    for (int i = tid; i < 54 * 54; i += blockDim.x) t_bond[i] = 1.5f;
    for (int i = tid; i < N; i += blockDim.x) { g_counts[i] = 0; g_cursor[i] = 0; }
    __syncthreads();
    if (tid == 0) {
        t_maxv[6]=4.f;  t_maxv[7]=3.f;  t_maxv[8]=2.f;  t_maxv[16]=6.f; t_maxv[9]=1.f;
        t_maxv[17]=1.f; t_maxv[35]=1.f; t_maxv[53]=1.f; t_maxv[15]=5.f; t_maxv[1]=1.f;
        t_vdw[1]=1.2f;  t_vdw[6]=1.7f;  t_vdw[7]=1.55f; t_vdw[8]=1.52f; t_vdw[9]=1.47f;
        t_vdw[15]=1.8f; t_vdw[16]=1.8f; t_vdw[17]=1.75f; t_vdw[35]=1.85f; t_vdw[53]=1.98f;
        const int   ba[14] = {6,6,6,6,6,6,6,7,7,7,8,8,16,15};
        const int   bb[14] = {6,7,8,16,9,17,1,7,8,1,8,1,16,8};
        const float bl[14] = {1.54f,1.47f,1.43f,1.82f,1.35f,1.77f,1.09f,
                              1.45f,1.40f,1.01f,1.48f,0.96f,2.05f,1.63f};
        for (int k = 0; k < 14; k++) {
            t_bond[ba[k] * 54 + bb[k]] = bl[k];
            t_bond[bb[k] * 54 + ba[k]] = bl[k];
        }
    }
}

// ---------------- K1: out-degree counts ----------------
__global__ void k_count(const int* __restrict__ row, int E) {
    int e = blockIdx.x * blockDim.x + threadIdx.x;
    if (e < E) atomicAdd(&g_counts[row[e]], 1);
}

// ---------------- K2: violation + rad8 + loss1 + CSR offsets (single-block scan) ----------------
__global__ void k_scan(const int* __restrict__ types, int N, int NI) {
    __shared__ int   ss[1024];
    __shared__ float sl[1024];
    int tid  = threadIdx.x;
    int base = tid * NI;
    int local[16];
    int   s = 0;
    float lloss = 0.0f;
    for (int k = 0; k < NI; k++) {
        int i = base + k;
        int c = 0;
        if (i < N) {
            c = g_counts[i];
            int z = types[i]; z = (z < 0) ? 0 : ((z > 53) ? 53 : z);
            float v = (float)c - t_maxv[z];
            if (v < 0.0f) v = 0.0f;
            g_viol[i] = v;
            lloss += v * v;
            g_rad8[i] = t_vdw[z] * 0.8f;
        }
        local[k] = s;
        s += c;
    }
    ss[tid] = s;
    sl[tid] = lloss;
    __syncthreads();
    // Hillis–Steele inclusive scan over per-thread sums
    for (int d = 1; d < 1024; d <<= 1) {
        int v = (tid >= d) ? ss[tid - d] : 0;
        __syncthreads();
        ss[tid] += v;
        __syncthreads();
    }
    int excl = ss[tid] - s;
    for (int k = 0; k < NI; k++) {
        int i = base + k;
        if (i < N) g_off[i] = excl + local[k];
    }
    if (tid == 0) g_off[N] = ss[1023];
    // loss1 block reduce
    for (int d = 512; d > 0; d >>= 1) {
        __syncthreads();
        if (tid < d) sl[tid] += sl[tid + d];
    }
    __syncthreads();
    if (tid == 0) g_loss1 = sl[0];
}

// ---------------- K3: CSR fill (unordered within row) ----------------
__global__ void k_fill(const int* __restrict__ row, int E) {
    int e = blockIdx.x * blockDim.x + threadIdx.x;
    if (e < E) {
        int r = row[e];
        int p = atomicAdd(&g_cursor[r], 1);
        g_csr[g_off[r] + p] = e;
    }
}

// ---------------- K4: per-row insertion sort -> original edge order (stable-sort semantics) ----------------
__global__ void k_sortrow(int N) {
    int i = blockIdx.x * blockDim.x + threadIdx.x;
    if (i >= N) return;
    int b = g_off[i], e2 = g_off[i + 1];
    for (int a = b + 1; a < e2; a++) {
        int key = g_csr[a];
        int t = a - 1;
        while (t >= b && g_csr[t] > key) { g_csr[t + 1] = g_csr[t]; t--; }
        g_csr[t + 1] = key;
    }
}

// ---------------- K5: one valence-push sweep (Jacobi toward the exact sequential scan) ----------------
// Within-row sequential order is exact; cols c<i read the previous sweep's
// result (converging to their final positions), cols c>=i read the original
// positions (their scan turn comes later) -- matching the scan's semantics.
__global__ void k_sweep(const float* __restrict__ orig, const float* __restrict__ prev,
                        float* __restrict__ out, const int* __restrict__ col,
                        int N, int writePos2) {
    int i = blockIdx.x * blockDim.x + threadIdx.x;
    if (i >= N) return;
    float x = orig[3 * i], y = orig[3 * i + 1], z = orig[3 * i + 2];
    float v = g_viol[i];
    if (v > 0.0f) {
        float s = v * 1e-3f;
        int b = g_off[i], e = g_off[i + 1];
        for (int k = b; k < e; k++) {
            int c = col[g_csr[k]];
            if (c == i) continue;                  // self-loop contributes exactly 0
            const float* pc = (c < i) ? prev : orig;
            float dx = x - pc[3 * c];
            float dy = y - pc[3 * c + 1];
            float dz = z - pc[3 * c + 2];
            float dist = sqrtf(dx * dx + dy * dy + dz * dz) + 1e-8f;
            float f = s / dist;
            x += dx * f; y += dy * f; z += dz * f;
        }
    }
    out[3 * i] = x; out[3 * i + 1] = y; out[3 * i + 2] = z;
    if (writePos2) { g_pos2[3 * i] = x; g_pos2[3 * i + 1] = y; g_pos2[3 * i + 2] = z; }
}

// ---------------- K6: bond-length correction + loss2 partials ----------------
__global__ void k_bond(const float* __restrict__ p1, const int* __restrict__ row,
                       const int* __restrict__ col, const int* __restrict__ types, int E) {
    __shared__ float sl[256];
    int tid = threadIdx.x;
    int e = blockIdx.x * blockDim.x + tid;
    float l = 0.0f;
    if (e < E) {
        int r = row[e], c = col[e];
        float dx = p1[3 * r]     - p1[3 * c];
        float dy = p1[3 * r + 1] - p1[3 * c + 1];
        float dz = p1[3 * r + 2] - p1[3 * c + 2];
        float cur = sqrtf(dx * dx + dy * dy + dz * dz);
        int zr = types[r]; zr = (zr < 0) ? 0 : ((zr > 53) ? 53 : zr);
        int zc = types[c]; zc = (zc < 0) ? 0 : ((zc > 53) ? 53 : zc);
        float tgt = t_bond[zr * 54 + zc];
        float df = cur - tgt;
        l = df * df;
        float ratio = tgt / (cur + 1e-8f);
        ratio = fminf(fmaxf(ratio, 0.98f), 1.02f);
        float sc = (ratio - 1.0f) * 0.01f * 0.5f;   // adj * 0.5 coefficient
        atomicAdd(&g_pos2[3 * r],     dx * sc);
        atomicAdd(&g_pos2[3 * r + 1], dy * sc);
        atomicAdd(&g_pos2[3 * r + 2], dz * sc);
        atomicAdd(&g_pos2[3 * c],    -dx * sc);
        atomicAdd(&g_pos2[3 * c + 1],-dy * sc);
        atomicAdd(&g_pos2[3 * c + 2],-dz * sc);
    }
    sl[tid] = l;
    for (int d = 128; d > 0; d >>= 1) {
        __syncthreads();
        if (tid < d) sl[tid] += sl[tid + d];
    }
    __syncthreads();
    if (tid == 0) g_l2part[blockIdx.x] = sl[0];
}

// ---------------- K7: pack (pos2, rad8) into float4 ----------------
__global__ void k_pack(int N) {
    int i = blockIdx.x * blockDim.x + threadIdx.x;
    if (i < N)
        g_pack[i] = make_float4(g_pos2[3 * i], g_pos2[3 * i + 1], g_pos2[3 * i + 2], g_rad8[i]);
}

// ---------------- K8: steric N^2 pass (FMA-bound fast path, rare rsqrt slow path) ----------------
__global__ void __launch_bounds__(256) k_steric(int N, int CH) {
    __shared__ float4 tile[TILE];
    __shared__ float  sl[256];
    int tid = threadIdx.x;
    int i = blockIdx.x * 256 + tid;
    bool valid = (i < N);
    float4 me = valid ? g_pack[i] : make_float4(1e30f, 1e30f, 1e30f, 0.0f);
    float csum = 0.0f, cvx = 0.0f, cvy = 0.0f, cvz = 0.0f, loss = 0.0f;
    int jbase = blockIdx.y * CH;
    int jend = jbase + CH; if (jend > N) jend = N;
    for (int t0 = jbase; t0 < jend; t0 += TILE) {
        __syncthreads();
        for (int k = tid; k < TILE; k += 256) {
            int jg = t0 + k;
            tile[k] = (jg < jend) ? g_pack[jg] : make_float4(1e30f, 1e30f, 1e30f, 0.0f);
        }
        __syncthreads();
        #pragma unroll 4
        for (int j = 0; j < TILE; j++) {
            float4 q = tile[j];                    // broadcast: all lanes same address
            float dx = me.x - q.x;
            float dy = me.y - q.y;
            float dz = me.z - q.z;
            float d2 = dx * dx + dy * dy + dz * dz;
            // coarse gate: max possible min_d^2 = ((1.98+1.98)*0.8)^2 = 10.036
            if (d2 < 10.05f) {
                int jg = t0 + j;
                if (jg != i) {
                    float mind = me.w + q.w;
                    if (d2 < mind * mind) {
                        float d2c = fmaxf(d2, 1e-20f);
                        float inv = rsqrtf(d2c);
                        float dist = d2c * inv;       // sqrt(d2)
                        float tt = mind - dist;
                        if (tt > 0.0f) {
                            loss += tt * tt;
                            if (dist > 1e-8f) {
                                float cc = tt * 0.0025f * inv;  // (min_d-dist)*0.005*0.5/dist
                                csum += cc;
                                cvx += cc * q.x;
                                cvy += cc * q.y;
                                cvz += cc * q.z;
                            }
                        }
                    }
                }
            }
        }
    }
    if (valid) g_part[blockIdx.y * N + i] = make_float4(csum, cvx, cvy, cvz);
    sl[tid] = loss;
    for (int d = 128; d > 0; d >>= 1) {
        __syncthreads();
        if (tid < d) sl[tid] += sl[tid + d];
    }
    __syncthreads();
    if (tid == 0) g_l3part[blockIdx.y * gridDim.x + blockIdx.x] = sl[0];
}

// ---------------- K9: combine partials -> output positions ----------------
__global__ void k_out(float* __restrict__ out, int N) {
    int i = blockIdx.x * blockDim.x + threadIdx.x;
    if (i >= N) return;
    float4 p = g_pack[i];
    float cs = 0.0f, vx = 0.0f, vy = 0.0f, vz = 0.0f;
    #pragma unroll
    for (int ch = 0; ch < NCH; ch++) {
        float4 t = g_part[ch * N + i];
        cs += t.x; vx += t.y; vy += t.z; vz += t.w;
    }
    out[3 * i]     = p.x + cs * p.x - vx;
    out[3 * i + 1] = p.y + cs * p.y - vy;
    out[3 * i + 2] = p.z + cs * p.z - vz;
}

// ---------------- K10: finalize loss (deterministic ordered sums) ----------------
__global__ void k_fin(float* __restrict__ out, int N, int E, int nb2, int nb3, int out_size) {
    if (threadIdx.x == 0) {
        float l2 = 0.0f;
        for (int b = 0; b < nb2; b++) l2 += g_l2part[b];
        l2 /= (float)E;
        float l3 = 0.0f;
        for (int b = 0; b < nb3; b++) l3 += g_l3part[b];
        out[3 * N] = (g_loss1 + l2 + l3 * 0.5f) * 0.1f;
    }
    // defensively zero any tail beyond 3N+1
    for (int k = 3 * N + 1 + (int)threadIdx.x; k < out_size; k += (int)blockDim.x)
        out[k] = 0.0f;
}

// ---------------- launcher ----------------
extern "C" void kernel_launch(void* const* d_in, const int* in_sizes, int n_in,
                              void* d_out, int out_size) {
    const float* pos   = (const float*)d_in[0];
    const int*   edge  = (const int*)d_in[1];
    const int*   types = (const int*)d_in[2];
    float*       out   = (float*)d_out;

    int N = in_sizes[0] / 3;
    int E = in_sizes[1] / 2;
    const int* row = edge;
    const int* col = edge + E;

    int nbN = (N + 255) / 256;
    int nbE = (E + 255) / 256;
    int NI  = (N + 1023) / 1024;
    int CH  = (N + NCH - 1) / NCH;

    k_init<<<1, 1024>>>(N);
    k_count<<<nbE, 256>>>(row, E);
    k_scan<<<1, 1024>>>(types, N, NI);
    k_fill<<<nbE, 256>>>(row, E);
    k_sortrow<<<nbN, 256>>>(N);
    // 3 Jacobi sweeps converge to the exact sequential scan (strictly lower-
    // triangular dependency, contraction ~1e-3 per hop)
    k_sweep<<<nbN, 256>>>(pos, pos,  g_pA, col, N, 0);
    k_sweep<<<nbN, 256>>>(pos, g_pA, g_pB, col, N, 0);
    k_sweep<<<nbN, 256>>>(pos, g_pB, g_pA, col, N, 1);   // also seeds g_pos2
    k_bond<<<nbE, 256>>>(g_pA, row, col, types, E);
    k_pack<<<nbN, 256>>>(N);
    dim3 sgrid(nbN, NCH);
    k_steric<<<sgrid, 256>>>(N, CH);
    k_out<<<nbN, 256>>>(out, N);
    k_fin<<<1, 32>>>(out, N, E, nbE, nbN * NCH, out_size);
}